// round 15
// baseline (speedup 1.0000x reference)
#include <cuda_runtime.h>
#include <cuda_fp16.h>

#define NN 100000
#define NE 1600000
#define NG 512
#define NOUT 10
#define NB_SCAN ((NN + 1023) / 1024)     // 98
#define NB_ZERO ((NN + 255) / 256)       // 391
#define NB_EDGE ((NE / 4 + 255) / 256)   // 1563
#define NB_XCONV 12500                   // NN*128/4/256
#define GEMM_BLOCKS (((NN + 127) / 128) * 2)   // 1564

// GEMM geometry: CTA = 128x64 output, 8 warps (4x2), warp tile 32x32.
// Whole K=128 resident in smem: A fp16 [128][136], W hi/lo [128][72] each.
#define SA_A 136                         // A smem row stride (halves)
#define SA_W 72                          // W smem row stride (halves)
#define A_HALVES (128 * SA_A)            // 17408
#define W_HALVES (128 * SA_W)            // 9216
#define SMEM_BYTES ((A_HALVES + 2 * W_HALVES) * 2)   // 71680 B

// ---------------- scratch (device globals; no allocation allowed) ----------
__device__ __align__(16) __half g_gh[(size_t)NN * 128];   // g = dinv*(h@W), fp16
__device__ __align__(16) __half g_ah[(size_t)NN * 128];   // activations, fp16
__device__ __align__(16) __half g_wh[4 * 128 * 128];      // weights hi (4 layers)
__device__ __align__(16) __half g_wl[4 * 128 * 128];      // weights lo
__device__ __align__(16) int    g_deg[NN];
__device__ __align__(16) int    g_fill[NN];
__device__ __align__(16) int    g_off[NN + 1];
__device__ __align__(16) unsigned long long g_scanstate[128];
__device__ __align__(16) int    g_csr[NE];

// ---------------- helpers ----------------------------------------------------
__device__ __forceinline__ void split2(float a, float b, unsigned& hi, unsigned& lo) {
    __half h0 = __float2half_rn(a), h1 = __float2half_rn(b);
    __half l0 = __float2half_rn(a - __half2float(h0));
    __half l1 = __float2half_rn(b - __half2float(h1));
    __half2 H = __halves2half2(h0, h1), L = __halves2half2(l0, l1);
    hi = *(unsigned*)&H; lo = *(unsigned*)&L;
}

__device__ __forceinline__ void mma16816(float* c, const unsigned* a, const unsigned* b) {
    asm volatile(
        "mma.sync.aligned.m16n8k16.row.col.f32.f16.f16.f32 "
        "{%0,%1,%2,%3}, {%4,%5,%6,%7}, {%8,%9}, {%0,%1,%2,%3};"
        : "+f"(c[0]), "+f"(c[1]), "+f"(c[2]), "+f"(c[3])
        : "r"(a[0]), "r"(a[1]), "r"(a[2]), "r"(a[3]), "r"(b[0]), "r"(b[1]));
}

__device__ __forceinline__ void cpa16(__half* dst_smem, const __half* src) {
    unsigned d = (unsigned)__cvta_generic_to_shared(dst_smem);
    asm volatile("cp.async.cg.shared.global [%0], [%1], 16;" :: "r"(d), "l"(src));
}

__device__ __forceinline__ void ldsm_x4(unsigned* r, const __half* p) {
    unsigned a = (unsigned)__cvta_generic_to_shared(p);
    asm volatile("ldmatrix.sync.aligned.m8n8.x4.shared.b16 {%0,%1,%2,%3}, [%4];"
                 : "=r"(r[0]), "=r"(r[1]), "=r"(r[2]), "=r"(r[3]) : "r"(a));
}

__device__ __forceinline__ void ldsm_x4t(unsigned* r, const __half* p) {
    unsigned a = (unsigned)__cvta_generic_to_shared(p);
    asm volatile("ldmatrix.sync.aligned.m8n8.x4.trans.shared.b16 {%0,%1,%2,%3}, [%4];"
                 : "=r"(r[0]), "=r"(r[1]), "=r"(r[2]), "=r"(r[3]) : "r"(a));
}

// ---------------- zero: deg + scan state -------------------------------------
__global__ void k_zero() {
    int i = blockIdx.x * 256 + threadIdx.x;
    if (i < NN) g_deg[i] = 0;
    if (blockIdx.x == 0 && threadIdx.x < 128) g_scanstate[threadIdx.x] = 0ULL;
}

// ---------------- fused prep: edge atomics + x conv + W split ----------------
__global__ void k_prep(const int* __restrict__ ei,
                       const float* __restrict__ x,
                       const float* __restrict__ W_in,
                       const float* __restrict__ W_hid) {
    int b = blockIdx.x;
    if (b < NB_EDGE) {
        int t = b * 256 + threadIdx.x;
        if (t < NE / 4) {
            int4 d = ((const int4*)(ei + NE))[t];
            atomicAdd(&g_deg[d.x], 1);
            atomicAdd(&g_deg[d.y], 1);
            atomicAdd(&g_deg[d.z], 1);
            atomicAdd(&g_deg[d.w], 1);
        }
    } else if (b < NB_EDGE + NB_XCONV) {
        size_t i = (size_t)(b - NB_EDGE) * 256 + threadIdx.x;   // float4 index
        float4 v = ((const float4*)x)[i];
        __half2 a = __floats2half2_rn(v.x, v.y);
        __half2 c = __floats2half2_rn(v.z, v.w);
        uint2 p; p.x = *(unsigned*)&a; p.y = *(unsigned*)&c;
        *(uint2*)(g_ah + i * 4) = p;
    } else {
        size_t wi = (size_t)(b - NB_EDGE - NB_XCONV) * 256 + threadIdx.x;
        if (wi < 16384) {
            float4 v = (wi < 4096) ? ((const float4*)W_in)[wi]
                                   : ((const float4*)W_hid)[wi - 4096];
            uint2 hi, lo;
            split2(v.x, v.y, hi.x, lo.x);
            split2(v.z, v.w, hi.y, lo.y);
            *(uint2*)(g_wh + wi * 4) = hi;
            *(uint2*)(g_wl + wi * 4) = lo;
        }
    }
}

// ---------------- fused scan (decoupled lookback): off + fill seed ----------
__global__ void k_scan_fused() {
    __shared__ int sm[1024];
    __shared__ int s_prefix;
    const int b = blockIdx.x;
    const int i = b * 1024 + threadIdx.x;
    const int v = (i < NN) ? g_deg[i] : 0;
    sm[threadIdx.x] = v;
    __syncthreads();
    for (int d = 1; d < 1024; d <<= 1) {
        int t = (threadIdx.x >= d) ? sm[threadIdx.x - d] : 0;
        __syncthreads();
        sm[threadIdx.x] += t;
        __syncthreads();
    }
    if (threadIdx.x == 0) {
        const unsigned total = (unsigned)sm[1023];
        if (b == 0) {
            atomicExch(&g_scanstate[0], (2ULL << 32) | total);   // inclusive
            s_prefix = 0;
        } else {
            atomicExch(&g_scanstate[b], (1ULL << 32) | total);   // aggregate
            int excl = 0;
            int pb = b - 1;
            while (true) {
                unsigned long long st = atomicAdd(&g_scanstate[pb], 0ULL);
                unsigned flag = (unsigned)(st >> 32);
                if (flag == 0) continue;                          // spin
                excl += (int)(st & 0xffffffffu);
                if (flag == 2u) break;
                pb--;
            }
            atomicExch(&g_scanstate[b], (2ULL << 32) | (unsigned)(total + excl));
            s_prefix = excl;
        }
    }
    __syncthreads();
    const int incl = sm[threadIdx.x] + s_prefix;
    if (i < NN) {
        int excl_i = incl - v;
        g_off[i]  = excl_i;
        g_fill[i] = excl_i;
        if (i == NN - 1) g_off[NN] = incl;
    }
}

// ---------------- tensor-core GEMM: g = fp16( dinv * (A @ W) ) ---------------
// Whole-K resident; A fp16; W split hi/lo (2-term MMA). CTA = 128x64.
// Layer 0: grid is extended by NB_EDGE blocks that perform the CSR fill —
// atomic-latency-bound fill warps interleave with L1-bound GEMM warps.
__global__ void __launch_bounds__(256, 3) k_gemm_tc(int layer,
                                                    const int* __restrict__ ei) {
    if (blockIdx.x >= GEMM_BLOCKS) {                 // CSR-fill blocks (layer 0)
        int t = (blockIdx.x - GEMM_BLOCKS) * 256 + threadIdx.x;
        if (t < NE / 4) {
            int4 s = ((const int4*)ei)[t];
            int4 d = ((const int4*)(ei + NE))[t];
            int p;
            p = atomicAdd(&g_fill[d.x], 1); g_csr[p] = s.x;
            p = atomicAdd(&g_fill[d.y], 1); g_csr[p] = s.y;
            p = atomicAdd(&g_fill[d.z], 1); g_csr[p] = s.z;
            p = atomicAdd(&g_fill[d.w], 1); g_csr[p] = s.w;
        }
        return;
    }

    extern __shared__ __half smh[];
    __half* As = smh;                        // [128][SA_A]
    __half* Wh = smh + A_HALVES;             // [128][SA_W]
    __half* Wl = smh + A_HALVES + W_HALVES;  // [128][SA_W]
    const int col0 = (blockIdx.x & 1) * 64;
    const int row0 = (blockIdx.x >> 1) * 128;
    const __half* Wbh = g_wh + (size_t)layer * 16384 + col0;
    const __half* Wbl = g_wl + (size_t)layer * 16384 + col0;
    const int tid = threadIdx.x;

    // single burst: whole A tile (128x128) + whole W hi/lo (128x64 each)
#pragma unroll
    for (int o = tid; o < 2048; o += 256) {           // A: 128 rows x 16 segs
        int r = o >> 4, seg = (o & 15) * 8;
        int grow = row0 + r;
        if (grow < NN)
            cpa16(As + r * SA_A + seg, g_ah + (size_t)grow * 128 + seg);
    }
#pragma unroll
    for (int o = tid; o < 2048; o += 256) {           // W: 128 rows x 8 segs x2
        int oo = o & 1023;
        int kr = oo >> 3, seg = (oo & 7) * 8;
        if (o < 1024)
            cpa16(Wh + kr * SA_W + seg, Wbh + (size_t)kr * 128 + seg);
        else
            cpa16(Wl + kr * SA_W + seg, Wbl + (size_t)kr * 128 + seg);
    }
    asm volatile("cp.async.commit_group;");

    const int lane = tid & 31, wid = tid >> 5;
    const int wm = wid >> 1, wn = wid & 1;               // 4x2 warp grid
    const int g = lane >> 2, t2 = (lane & 3) << 1;
    const int lr = lane & 7, sel = lane >> 3;
    const int a_row_off = (sel & 1) * 8;
    const int a_col_off = (sel & 2) * 4;
    const int w_krow = lane & 15;
    const int w_noff = (lane >> 4) * 8;

    float acc[2][4][4];
#pragma unroll
    for (int mt = 0; mt < 2; mt++)
#pragma unroll
        for (int nt = 0; nt < 4; nt++)
#pragma unroll
            for (int q = 0; q < 4; q++) acc[mt][nt][q] = 0.f;

    asm volatile("cp.async.wait_group 0;");
    __syncthreads();

#pragma unroll
    for (int ks = 0; ks < 8; ks++) {
        const int kc = ks * 16;
        unsigned bh2[2][4], bl2[2][4];
#pragma unroll
        for (int nh = 0; nh < 2; nh++) {
            const __half* pw = Wh + (kc + w_krow) * SA_W + wn * 32 + nh * 16 + w_noff;
            ldsm_x4t(bh2[nh], pw);
            const __half* pl = Wl + (kc + w_krow) * SA_W + wn * 32 + nh * 16 + w_noff;
            ldsm_x4t(bl2[nh], pl);
        }
#pragma unroll
        for (int mt = 0; mt < 2; mt++) {
            const int m0 = wm * 32 + mt * 16;
            unsigned a_[4];
            ldsm_x4(a_, As + (m0 + lr + a_row_off) * SA_A + kc + a_col_off);
#pragma unroll
            for (int nt = 0; nt < 4; nt++) {
                unsigned bhf[2] = {bh2[nt >> 1][(nt & 1) * 2],
                                   bh2[nt >> 1][(nt & 1) * 2 + 1]};
                unsigned blf[2] = {bl2[nt >> 1][(nt & 1) * 2],
                                   bl2[nt >> 1][(nt & 1) * 2 + 1]};
                mma16816(acc[mt][nt], a_, bhf);   // A @ Wh
                mma16816(acc[mt][nt], a_, blf);   // A @ Wl
            }
        }
    }

    // epilogue: scale by dinv (from deg), pack fp16, store
#pragma unroll
    for (int mt = 0; mt < 2; mt++) {
        int r0 = row0 + wm * 32 + mt * 16 + g;
        int r1 = r0 + 8;
        float d0 = (r0 < NN) ? rsqrtf((float)(g_deg[r0] + 1)) : 0.f;
        float d1 = (r1 < NN) ? rsqrtf((float)(g_deg[r1] + 1)) : 0.f;
#pragma unroll
        for (int nt = 0; nt < 4; nt++) {
            int n = col0 + wn * 32 + nt * 8 + t2;
            if (r0 < NN) {
                __half2 p = __floats2half2_rn(acc[mt][nt][0] * d0, acc[mt][nt][1] * d0);
                *(__half2*)(g_gh + (size_t)r0 * 128 + n) = p;
            }
            if (r1 < NN) {
                __half2 p = __floats2half2_rn(acc[mt][nt][2] * d1, acc[mt][nt][3] * d1);
                *(__half2*)(g_gh + (size_t)r1 * 128 + n) = p;
            }
        }
    }
}

// ---------------- aggregation (gather CSR; 4 edges in flight) ---------------
__global__ void __launch_bounds__(256) k_agg(const float* __restrict__ bias) {
    int n = (blockIdx.x * blockDim.x + threadIdx.x) >> 5;
    int lane = threadIdx.x & 31;
    if (n >= NN) return;
    const uint2* gb = (const uint2*)g_gh;       // 8B units; row stride = 32
    uint2 sv = gb[(size_t)n * 32 + lane];       // self-loop term
    __half2 h0 = *(__half2*)&sv.x, h1 = *(__half2*)&sv.y;
    float2 f0 = __half22float2(h0), f1 = __half22float2(h1);
    float4 acc = make_float4(f0.x, f0.y, f1.x, f1.y);

    int s = g_off[n], e = g_off[n + 1];
    for (int base = s; base < e; base += 32) {
        int cnt = e - base; if (cnt > 32) cnt = 32;
        int id = (lane < cnt) ? g_csr[base + lane] : 0;
        int j = 0;
        for (; j + 4 <= cnt; j += 4) {          // two independent HADD2 pairs
            int s0 = __shfl_sync(0xffffffffu, id, j);
            int s1 = __shfl_sync(0xffffffffu, id, j + 1);
            int s2 = __shfl_sync(0xffffffffu, id, j + 2);
            int s3 = __shfl_sync(0xffffffffu, id, j + 3);
            uint2 va = gb[(size_t)s0 * 32 + lane];
            uint2 vb = gb[(size_t)s1 * 32 + lane];
            uint2 vc = gb[(size_t)s2 * 32 + lane];
            uint2 vd = gb[(size_t)s3 * 32 + lane];
            __half2 p0 = __hadd2(*(__half2*)&va.x, *(__half2*)&vb.x);
            __half2 p1 = __hadd2(*(__half2*)&va.y, *(__half2*)&vb.y);
            __half2 q0 = __hadd2(*(__half2*)&vc.x, *(__half2*)&vd.x);
            __half2 q1 = __hadd2(*(__half2*)&vc.y, *(__half2*)&vd.y);
            float2 a0 = __half22float2(p0), a1 = __half22float2(p1);
            float2 b0 = __half22float2(q0), b1 = __half22float2(q1);
            acc.x += a0.x + b0.x; acc.y += a0.y + b0.y;
            acc.z += a1.x + b1.x; acc.w += a1.y + b1.y;
        }
        if (j + 2 <= cnt) {
            int s0 = __shfl_sync(0xffffffffu, id, j);
            int s1 = __shfl_sync(0xffffffffu, id, j + 1);
            uint2 va = gb[(size_t)s0 * 32 + lane];
            uint2 vb = gb[(size_t)s1 * 32 + lane];
            __half2 p0 = __hadd2(*(__half2*)&va.x, *(__half2*)&vb.x);
            __half2 p1 = __hadd2(*(__half2*)&va.y, *(__half2*)&vb.y);
            float2 a0 = __half22float2(p0), a1 = __half22float2(p1);
            acc.x += a0.x; acc.y += a0.y; acc.z += a1.x; acc.w += a1.y;
            j += 2;
        }
        if (j < cnt) {
            int s0 = __shfl_sync(0xffffffffu, id, j);
            uint2 va = gb[(size_t)s0 * 32 + lane];
            float2 a0 = __half22float2(*(__half2*)&va.x);
            float2 a1 = __half22float2(*(__half2*)&va.y);
            acc.x += a0.x; acc.y += a0.y; acc.z += a1.x; acc.w += a1.y;
        }
    }
    float dn = rsqrtf((float)(g_deg[n] + 1));
    float4 bb = *(const float4*)(bias + lane * 4);
    __half2 o0 = __floats2half2_rn(acc.x * dn + bb.x, acc.y * dn + bb.y);
    __half2 o1 = __floats2half2_rn(acc.z * dn + bb.z, acc.w * dn + bb.w);
    uint2 p; p.x = *(unsigned*)&o0; p.y = *(unsigned*)&o1;
    *(uint2*)(g_ah + (size_t)n * 128 + lane * 4) = p;
}

// ---------------- mean pool per graph + output head -------------------------
__global__ void __launch_bounds__(128) k_pool(const int* __restrict__ batch,
                                              const float* __restrict__ Wout,
                                              const float* __restrict__ bout,
                                              float* __restrict__ out) {
    int gid = blockIdx.x;
    int c = threadIdx.x;
    int lo = 0, hi = NN;
    while (lo < hi) { int m = (lo + hi) >> 1; if (batch[m] < gid) lo = m + 1; else hi = m; }
    int start = lo;
    hi = NN;
    while (lo < hi) { int m = (lo + hi) >> 1; if (batch[m] < gid + 1) lo = m + 1; else hi = m; }
    int end = lo;

    float s = 0.f;
    for (int r = start; r < end; r++)
        s += __half2float(g_ah[(size_t)r * 128 + c]);
    __shared__ float pooled[128];
    int cnt = end - start;
    pooled[c] = (cnt > 0) ? s / (float)cnt : 0.f;
    __syncthreads();
    if (c < NOUT) {
        float a = bout[c];
#pragma unroll 8
        for (int k = 0; k < 128; k++) a += pooled[k] * Wout[k * NOUT + c];
        out[gid * NOUT + c] = a;
    }
}

// ---------------- launch (single stream; fill fused into gemm0) --------------
extern "C" void kernel_launch(void* const* d_in, const int* in_sizes, int n_in,
                              void* d_out, int out_size) {
    const float* x      = (const float*)d_in[0];
    const int*   ei     = (const int*)d_in[1];     // int32 (JAX x64 disabled)
    const int*   batch  = (const int*)d_in[2];     // int32
    const float* W_in   = (const float*)d_in[3];
    const float* b_in   = (const float*)d_in[4];
    const float* W_hid  = (const float*)d_in[5];
    const float* b_hid  = (const float*)d_in[6];
    const float* W_out  = (const float*)d_in[7];
    const float* b_out  = (const float*)d_in[8];
    float* out = (float*)d_out;

    cudaFuncSetAttribute(k_gemm_tc, cudaFuncAttributeMaxDynamicSharedMemorySize,
                         SMEM_BYTES);

    const int agg_blocks = (NN * 32 + 255) / 256;

    // gemm0(+fill) kept as 4th launch (ncu capture slot)
    k_zero<<<NB_ZERO, 256>>>();
    k_prep<<<NB_EDGE + NB_XCONV + 64, 256>>>(ei, x, W_in, W_hid);
    k_scan_fused<<<NB_SCAN, 1024>>>();
    k_gemm_tc<<<GEMM_BLOCKS + NB_EDGE, 256, SMEM_BYTES>>>(0, ei);  // <- profiled
    k_agg<<<agg_blocks, 256>>>(b_in);
    for (int i = 0; i < 3; i++) {
        k_gemm_tc<<<GEMM_BLOCKS, 256, SMEM_BYTES>>>(i + 1, ei);
        k_agg<<<agg_blocks, 256>>>(b_hid + (size_t)i * 128);
    }

    k_pool<<<NG, 128>>>(batch, W_out, b_out, out);
}

// round 16
// speedup vs baseline: 1.0687x; 1.0687x over previous
#include <cuda_runtime.h>
#include <cuda_fp16.h>

#define NN 100000
#define NE 1600000
#define NG 512
#define NOUT 10
#define NB_SCAN ((NN + 1023) / 1024)     // 98
#define NB_ZERO ((NN + 255) / 256)       // 391
#define NB_EDGE ((NE / 4 + 255) / 256)   // 1563
#define NB_XCONV 12500                   // NN*128/4/256
#define GEMM_BLOCKS (((NN + 127) / 128) * 2)   // 1564

// GEMM geometry: CTA = 128x64 output, 8 warps (4x2), warp tile 32x32.
// Whole K=128 resident in smem: A fp16 [128][136], W fp16 [128][72].
#define SA_A 136                         // A smem row stride (halves)
#define SA_W 72                          // W smem row stride (halves)
#define A_HALVES (128 * SA_A)            // 17408
#define W_HALVES (128 * SA_W)            // 9216
#define SMEM_BYTES ((A_HALVES + W_HALVES) * 2)   // 53248 B

// ---------------- scratch (device globals; no allocation allowed) ----------
__device__ __align__(16) __half g_gh[(size_t)NN * 128];   // g = dinv*(h@W), fp16
__device__ __align__(16) __half g_ah[(size_t)NN * 128];   // activations, fp16
__device__ __align__(16) __half g_wh[4 * 128 * 128];      // weights fp16 (4 layers)
__device__ __align__(16) int    g_deg[NN];
__device__ __align__(16) int    g_fill[NN];
__device__ __align__(16) int    g_off[NN + 1];
__device__ __align__(16) unsigned long long g_scanstate[128];
__device__ __align__(16) int    g_csr[NE];

// ---------------- helpers ----------------------------------------------------
__device__ __forceinline__ void mma16816(float* c, const unsigned* a, const unsigned* b) {
    asm volatile(
        "mma.sync.aligned.m16n8k16.row.col.f32.f16.f16.f32 "
        "{%0,%1,%2,%3}, {%4,%5,%6,%7}, {%8,%9}, {%0,%1,%2,%3};"
        : "+f"(c[0]), "+f"(c[1]), "+f"(c[2]), "+f"(c[3])
        : "r"(a[0]), "r"(a[1]), "r"(a[2]), "r"(a[3]), "r"(b[0]), "r"(b[1]));
}

__device__ __forceinline__ void cpa16(__half* dst_smem, const __half* src) {
    unsigned d = (unsigned)__cvta_generic_to_shared(dst_smem);
    asm volatile("cp.async.cg.shared.global [%0], [%1], 16;" :: "r"(d), "l"(src));
}

__device__ __forceinline__ void ldsm_x4(unsigned* r, const __half* p) {
    unsigned a = (unsigned)__cvta_generic_to_shared(p);
    asm volatile("ldmatrix.sync.aligned.m8n8.x4.shared.b16 {%0,%1,%2,%3}, [%4];"
                 : "=r"(r[0]), "=r"(r[1]), "=r"(r[2]), "=r"(r[3]) : "r"(a));
}

__device__ __forceinline__ void ldsm_x4t(unsigned* r, const __half* p) {
    unsigned a = (unsigned)__cvta_generic_to_shared(p);
    asm volatile("ldmatrix.sync.aligned.m8n8.x4.trans.shared.b16 {%0,%1,%2,%3}, [%4];"
                 : "=r"(r[0]), "=r"(r[1]), "=r"(r[2]), "=r"(r[3]) : "r"(a));
}

// ---------------- zero: deg + scan state -------------------------------------
__global__ void k_zero() {
    int i = blockIdx.x * 256 + threadIdx.x;
    if (i < NN) g_deg[i] = 0;
    if (blockIdx.x == 0 && threadIdx.x < 128) g_scanstate[threadIdx.x] = 0ULL;
}

// ---------------- fused prep: edge atomics + x conv + W conv -----------------
__global__ void k_prep(const int* __restrict__ ei,
                       const float* __restrict__ x,
                       const float* __restrict__ W_in,
                       const float* __restrict__ W_hid) {
    int b = blockIdx.x;
    if (b < NB_EDGE) {
        int t = b * 256 + threadIdx.x;
        if (t < NE / 4) {
            int4 d = ((const int4*)(ei + NE))[t];
            atomicAdd(&g_deg[d.x], 1);
            atomicAdd(&g_deg[d.y], 1);
            atomicAdd(&g_deg[d.z], 1);
            atomicAdd(&g_deg[d.w], 1);
        }
    } else if (b < NB_EDGE + NB_XCONV) {
        size_t i = (size_t)(b - NB_EDGE) * 256 + threadIdx.x;   // float4 index
        float4 v = ((const float4*)x)[i];
        __half2 a = __floats2half2_rn(v.x, v.y);
        __half2 c = __floats2half2_rn(v.z, v.w);
        uint2 p; p.x = *(unsigned*)&a; p.y = *(unsigned*)&c;
        *(uint2*)(g_ah + i * 4) = p;
    } else {
        size_t wi = (size_t)(b - NB_EDGE - NB_XCONV) * 256 + threadIdx.x;
        if (wi < 16384) {
            float4 v = (wi < 4096) ? ((const float4*)W_in)[wi]
                                   : ((const float4*)W_hid)[wi - 4096];
            __half2 a = __floats2half2_rn(v.x, v.y);
            __half2 c = __floats2half2_rn(v.z, v.w);
            uint2 p; p.x = *(unsigned*)&a; p.y = *(unsigned*)&c;
            *(uint2*)(g_wh + wi * 4) = p;
        }
    }
}

// ---------------- fused scan (decoupled lookback): off + fill seed ----------
__global__ void k_scan_fused() {
    __shared__ int sm[1024];
    __shared__ int s_prefix;
    const int b = blockIdx.x;
    const int i = b * 1024 + threadIdx.x;
    const int v = (i < NN) ? g_deg[i] : 0;
    sm[threadIdx.x] = v;
    __syncthreads();
    for (int d = 1; d < 1024; d <<= 1) {
        int t = (threadIdx.x >= d) ? sm[threadIdx.x - d] : 0;
        __syncthreads();
        sm[threadIdx.x] += t;
        __syncthreads();
    }
    if (threadIdx.x == 0) {
        const unsigned total = (unsigned)sm[1023];
        if (b == 0) {
            atomicExch(&g_scanstate[0], (2ULL << 32) | total);   // inclusive
            s_prefix = 0;
        } else {
            atomicExch(&g_scanstate[b], (1ULL << 32) | total);   // aggregate
            int excl = 0;
            int pb = b - 1;
            while (true) {
                unsigned long long st = atomicAdd(&g_scanstate[pb], 0ULL);
                unsigned flag = (unsigned)(st >> 32);
                if (flag == 0) continue;                          // spin
                excl += (int)(st & 0xffffffffu);
                if (flag == 2u) break;
                pb--;
            }
            atomicExch(&g_scanstate[b], (2ULL << 32) | (unsigned)(total + excl));
            s_prefix = excl;
        }
    }
    __syncthreads();
    const int incl = sm[threadIdx.x] + s_prefix;
    if (i < NN) {
        int excl_i = incl - v;
        g_off[i]  = excl_i;
        g_fill[i] = excl_i;
        if (i == NN - 1) g_off[NN] = incl;
    }
}

__global__ void k_fill(const int* __restrict__ ei) {
    int t = blockIdx.x * blockDim.x + threadIdx.x;
    if (t < NE / 4) {
        int4 s = ((const int4*)ei)[t];
        int4 d = ((const int4*)(ei + NE))[t];
        int p;
        p = atomicAdd(&g_fill[d.x], 1); g_csr[p] = s.x;
        p = atomicAdd(&g_fill[d.y], 1); g_csr[p] = s.y;
        p = atomicAdd(&g_fill[d.z], 1); g_csr[p] = s.z;
        p = atomicAdd(&g_fill[d.w], 1); g_csr[p] = s.w;
    }
}

// ---------------- tensor-core GEMM: g = fp16( dinv * (A @ W) ) ---------------
// Whole-K resident: one cp.async burst, one wait, one sync, then 8 k-steps of
// MMA with zero barriers. A fp16; W fp16 (single term). CTA = 128x64.
__global__ void __launch_bounds__(256, 3) k_gemm_tc(int layer) {
    extern __shared__ __half smh[];
    __half* As = smh;                        // [128][SA_A]
    __half* Wh = smh + A_HALVES;             // [128][SA_W]
    const int col0 = (blockIdx.x & 1) * 64;
    const int row0 = (blockIdx.x >> 1) * 128;
    const __half* Wbh = g_wh + (size_t)layer * 16384 + col0;
    const int tid = threadIdx.x;

    // single burst: whole A tile (128x128) + whole W (128x64)
#pragma unroll
    for (int o = tid; o < 2048; o += 256) {           // A: 128 rows x 16 segs
        int r = o >> 4, seg = (o & 15) * 8;
        int grow = row0 + r;
        if (grow < NN)
            cpa16(As + r * SA_A + seg, g_ah + (size_t)grow * 128 + seg);
    }
#pragma unroll
    for (int o = tid; o < 1024; o += 256) {           // W: 128 rows x 8 segs
        int kr = o >> 3, seg = (o & 7) * 8;
        cpa16(Wh + kr * SA_W + seg, Wbh + (size_t)kr * 128 + seg);
    }
    asm volatile("cp.async.commit_group;");

    const int lane = tid & 31, wid = tid >> 5;
    const int wm = wid >> 1, wn = wid & 1;               // 4x2 warp grid
    const int g = lane >> 2, t2 = (lane & 3) << 1;
    const int lr = lane & 7, sel = lane >> 3;
    const int a_row_off = (sel & 1) * 8;
    const int a_col_off = (sel & 2) * 4;
    const int w_krow = lane & 15;
    const int w_noff = (lane >> 4) * 8;

    float acc[2][4][4];
#pragma unroll
    for (int mt = 0; mt < 2; mt++)
#pragma unroll
        for (int nt = 0; nt < 4; nt++)
#pragma unroll
            for (int q = 0; q < 4; q++) acc[mt][nt][q] = 0.f;

    asm volatile("cp.async.wait_group 0;");
    __syncthreads();

#pragma unroll
    for (int ks = 0; ks < 8; ks++) {
        const int kc = ks * 16;
        unsigned bh2[2][4];
#pragma unroll
        for (int nh = 0; nh < 2; nh++) {
            const __half* pw = Wh + (kc + w_krow) * SA_W + wn * 32 + nh * 16 + w_noff;
            ldsm_x4t(bh2[nh], pw);
        }
#pragma unroll
        for (int mt = 0; mt < 2; mt++) {
            const int m0 = wm * 32 + mt * 16;
            unsigned a_[4];
            ldsm_x4(a_, As + (m0 + lr + a_row_off) * SA_A + kc + a_col_off);
#pragma unroll
            for (int nt = 0; nt < 4; nt++) {
                unsigned bhf[2] = {bh2[nt >> 1][(nt & 1) * 2],
                                   bh2[nt >> 1][(nt & 1) * 2 + 1]};
                mma16816(acc[mt][nt], a_, bhf);   // A @ W
            }
        }
    }

    // epilogue: scale by dinv (from deg), pack fp16, store
#pragma unroll
    for (int mt = 0; mt < 2; mt++) {
        int r0 = row0 + wm * 32 + mt * 16 + g;
        int r1 = r0 + 8;
        float d0 = (r0 < NN) ? rsqrtf((float)(g_deg[r0] + 1)) : 0.f;
        float d1 = (r1 < NN) ? rsqrtf((float)(g_deg[r1] + 1)) : 0.f;
#pragma unroll
        for (int nt = 0; nt < 4; nt++) {
            int n = col0 + wn * 32 + nt * 8 + t2;
            if (r0 < NN) {
                __half2 p = __floats2half2_rn(acc[mt][nt][0] * d0, acc[mt][nt][1] * d0);
                *(__half2*)(g_gh + (size_t)r0 * 128 + n) = p;
            }
            if (r1 < NN) {
                __half2 p = __floats2half2_rn(acc[mt][nt][2] * d1, acc[mt][nt][3] * d1);
                *(__half2*)(g_gh + (size_t)r1 * 128 + n) = p;
            }
        }
    }
}

// ---------------- aggregation (gather CSR; 4 edges in flight) ---------------
__global__ void __launch_bounds__(256) k_agg(const float* __restrict__ bias) {
    int n = (blockIdx.x * blockDim.x + threadIdx.x) >> 5;
    int lane = threadIdx.x & 31;
    if (n >= NN) return;
    const uint2* gb = (const uint2*)g_gh;       // 8B units; row stride = 32
    uint2 sv = gb[(size_t)n * 32 + lane];       // self-loop term
    __half2 h0 = *(__half2*)&sv.x, h1 = *(__half2*)&sv.y;
    float2 f0 = __half22float2(h0), f1 = __half22float2(h1);
    float4 acc = make_float4(f0.x, f0.y, f1.x, f1.y);

    int s = g_off[n], e = g_off[n + 1];
    for (int base = s; base < e; base += 32) {
        int cnt = e - base; if (cnt > 32) cnt = 32;
        int id = (lane < cnt) ? g_csr[base + lane] : 0;
        int j = 0;
        for (; j + 4 <= cnt; j += 4) {          // two independent HADD2 pairs
            int s0 = __shfl_sync(0xffffffffu, id, j);
            int s1 = __shfl_sync(0xffffffffu, id, j + 1);
            int s2 = __shfl_sync(0xffffffffu, id, j + 2);
            int s3 = __shfl_sync(0xffffffffu, id, j + 3);
            uint2 va = gb[(size_t)s0 * 32 + lane];
            uint2 vb = gb[(size_t)s1 * 32 + lane];
            uint2 vc = gb[(size_t)s2 * 32 + lane];
            uint2 vd = gb[(size_t)s3 * 32 + lane];
            __half2 p0 = __hadd2(*(__half2*)&va.x, *(__half2*)&vb.x);
            __half2 p1 = __hadd2(*(__half2*)&va.y, *(__half2*)&vb.y);
            __half2 q0 = __hadd2(*(__half2*)&vc.x, *(__half2*)&vd.x);
            __half2 q1 = __hadd2(*(__half2*)&vc.y, *(__half2*)&vd.y);
            float2 a0 = __half22float2(p0), a1 = __half22float2(p1);
            float2 b0 = __half22float2(q0), b1 = __half22float2(q1);
            acc.x += a0.x + b0.x; acc.y += a0.y + b0.y;
            acc.z += a1.x + b1.x; acc.w += a1.y + b1.y;
        }
        if (j + 2 <= cnt) {
            int s0 = __shfl_sync(0xffffffffu, id, j);
            int s1 = __shfl_sync(0xffffffffu, id, j + 1);
            uint2 va = gb[(size_t)s0 * 32 + lane];
            uint2 vb = gb[(size_t)s1 * 32 + lane];
            __half2 p0 = __hadd2(*(__half2*)&va.x, *(__half2*)&vb.x);
            __half2 p1 = __hadd2(*(__half2*)&va.y, *(__half2*)&vb.y);
            float2 a0 = __half22float2(p0), a1 = __half22float2(p1);
            acc.x += a0.x; acc.y += a0.y; acc.z += a1.x; acc.w += a1.y;
            j += 2;
        }
        if (j < cnt) {
            int s0 = __shfl_sync(0xffffffffu, id, j);
            uint2 va = gb[(size_t)s0 * 32 + lane];
            float2 a0 = __half22float2(*(__half2*)&va.x);
            float2 a1 = __half22float2(*(__half2*)&va.y);
            acc.x += a0.x; acc.y += a0.y; acc.z += a1.x; acc.w += a1.y;
        }
    }
    float dn = rsqrtf((float)(g_deg[n] + 1));
    float4 bb = *(const float4*)(bias + lane * 4);
    __half2 o0 = __floats2half2_rn(acc.x * dn + bb.x, acc.y * dn + bb.y);
    __half2 o1 = __floats2half2_rn(acc.z * dn + bb.z, acc.w * dn + bb.w);
    uint2 p; p.x = *(unsigned*)&o0; p.y = *(unsigned*)&o1;
    *(uint2*)(g_ah + (size_t)n * 128 + lane * 4) = p;
}

// ---------------- mean pool per graph + output head -------------------------
__global__ void __launch_bounds__(128) k_pool(const int* __restrict__ batch,
                                              const float* __restrict__ Wout,
                                              const float* __restrict__ bout,
                                              float* __restrict__ out) {
    int gid = blockIdx.x;
    int c = threadIdx.x;
    int lo = 0, hi = NN;
    while (lo < hi) { int m = (lo + hi) >> 1; if (batch[m] < gid) lo = m + 1; else hi = m; }
    int start = lo;
    hi = NN;
    while (lo < hi) { int m = (lo + hi) >> 1; if (batch[m] < gid + 1) lo = m + 1; else hi = m; }
    int end = lo;

    float s = 0.f;
    for (int r = start; r < end; r++)
        s += __half2float(g_ah[(size_t)r * 128 + c]);
    __shared__ float pooled[128];
    int cnt = end - start;
    pooled[c] = (cnt > 0) ? s / (float)cnt : 0.f;
    __syncthreads();
    if (c < NOUT) {
        float a = bout[c];
#pragma unroll 8
        for (int k = 0; k < 128; k++) a += pooled[k] * Wout[k * NOUT + c];
        out[gid * NOUT + c] = a;
    }
}

// ---------------- launch (single stream; round-14 structure) -----------------
extern "C" void kernel_launch(void* const* d_in, const int* in_sizes, int n_in,
                              void* d_out, int out_size) {
    const float* x      = (const float*)d_in[0];
    const int*   ei     = (const int*)d_in[1];     // int32 (JAX x64 disabled)
    const int*   batch  = (const int*)d_in[2];     // int32
    const float* W_in   = (const float*)d_in[3];
    const float* b_in   = (const float*)d_in[4];
    const float* W_hid  = (const float*)d_in[5];
    const float* b_hid  = (const float*)d_in[6];
    const float* W_out  = (const float*)d_in[7];
    const float* b_out  = (const float*)d_in[8];
    float* out = (float*)d_out;

    cudaFuncSetAttribute(k_gemm_tc, cudaFuncAttributeMaxDynamicSharedMemorySize,
                         SMEM_BYTES);

    const int agg_blocks = (NN * 32 + 255) / 256;

    // gemm0 kept as 4th launch (ncu capture slot)
    k_zero<<<NB_ZERO, 256>>>();
    k_prep<<<NB_EDGE + NB_XCONV + 64, 256>>>(ei, x, W_in, W_hid);
    k_scan_fused<<<NB_SCAN, 1024>>>();
    k_gemm_tc<<<GEMM_BLOCKS, 256, SMEM_BYTES>>>(0);          // <- profiled
    k_fill<<<NB_EDGE, 256>>>(ei);

    k_agg<<<agg_blocks, 256>>>(b_in);
    for (int i = 0; i < 3; i++) {
        k_gemm_tc<<<GEMM_BLOCKS, 256, SMEM_BYTES>>>(i + 1);
        k_agg<<<agg_blocks, 256>>>(b_hid + (size_t)i * 128);
    }

    k_pool<<<NG, 128>>>(batch, W_out, b_out, out);
}

// round 17
// speedup vs baseline: 1.0819x; 1.0123x over previous
#include <cuda_runtime.h>
#include <cuda_fp16.h>

#define NN 100000
#define NE 1600000
#define NG 512
#define NOUT 10
#define NB_SCAN ((NN + 1023) / 1024)     // 98
#define NB_ZERO ((NN + 255) / 256)       // 391
#define NB_EDGE ((NE / 4 + 255) / 256)   // 1563
#define NB_FILL ((NE / 8 + 255) / 256)   // 782
#define NB_XCONV 12500                   // NN*128/4/256
#define GEMM_BLOCKS (((NN + 127) / 128) * 2)   // 1564

// GEMM geometry: CTA = 128x64 output, 8 warps (4x2), warp tile 32x32.
// Whole K=128 resident in smem: A fp16 [128][136], W fp16 [128][72].
#define SA_A 136                         // A smem row stride (halves)
#define SA_W 72                          // W smem row stride (halves)
#define A_HALVES (128 * SA_A)            // 17408
#define W_HALVES (128 * SA_W)            // 9216
#define SMEM_BYTES ((A_HALVES + W_HALVES) * 2)   // 53248 B -> 4 CTAs/SM

// ---------------- scratch (device globals; no allocation allowed) ----------
__device__ __align__(16) __half g_gh[(size_t)NN * 128];   // g = dinv*(h@W), fp16
__device__ __align__(16) __half g_ah[(size_t)NN * 128];   // activations, fp16
__device__ __align__(16) __half g_wh[4 * 128 * 128];      // weights fp16 (4 layers)
__device__ __align__(16) int    g_deg[NN];
__device__ __align__(16) int    g_fill[NN];
__device__ __align__(16) int    g_off[NN + 1];
__device__ __align__(16) unsigned long long g_scanstate[128];
__device__ __align__(16) int    g_csr[NE];

// ---------------- helpers ----------------------------------------------------
__device__ __forceinline__ void mma16816(float* c, const unsigned* a, const unsigned* b) {
    asm volatile(
        "mma.sync.aligned.m16n8k16.row.col.f32.f16.f16.f32 "
        "{%0,%1,%2,%3}, {%4,%5,%6,%7}, {%8,%9}, {%0,%1,%2,%3};"
        : "+f"(c[0]), "+f"(c[1]), "+f"(c[2]), "+f"(c[3])
        : "r"(a[0]), "r"(a[1]), "r"(a[2]), "r"(a[3]), "r"(b[0]), "r"(b[1]));
}

__device__ __forceinline__ void cpa16(__half* dst_smem, const __half* src) {
    unsigned d = (unsigned)__cvta_generic_to_shared(dst_smem);
    asm volatile("cp.async.cg.shared.global [%0], [%1], 16;" :: "r"(d), "l"(src));
}

__device__ __forceinline__ void ldsm_x4(unsigned* r, const __half* p) {
    unsigned a = (unsigned)__cvta_generic_to_shared(p);
    asm volatile("ldmatrix.sync.aligned.m8n8.x4.shared.b16 {%0,%1,%2,%3}, [%4];"
                 : "=r"(r[0]), "=r"(r[1]), "=r"(r[2]), "=r"(r[3]) : "r"(a));
}

__device__ __forceinline__ void ldsm_x4t(unsigned* r, const __half* p) {
    unsigned a = (unsigned)__cvta_generic_to_shared(p);
    asm volatile("ldmatrix.sync.aligned.m8n8.x4.trans.shared.b16 {%0,%1,%2,%3}, [%4];"
                 : "=r"(r[0]), "=r"(r[1]), "=r"(r[2]), "=r"(r[3]) : "r"(a));
}

// ---------------- zero: deg + scan state -------------------------------------
__global__ void k_zero() {
    int i = blockIdx.x * 256 + threadIdx.x;
    if (i < NN) g_deg[i] = 0;
    if (blockIdx.x == 0 && threadIdx.x < 128) g_scanstate[threadIdx.x] = 0ULL;
}

// ---------------- fused prep: edge atomics + x conv + W conv -----------------
__global__ void k_prep(const int* __restrict__ ei,
                       const float* __restrict__ x,
                       const float* __restrict__ W_in,
                       const float* __restrict__ W_hid) {
    int b = blockIdx.x;
    if (b < NB_EDGE) {
        int t = b * 256 + threadIdx.x;
        if (t < NE / 4) {
            int4 d = ((const int4*)(ei + NE))[t];
            atomicAdd(&g_deg[d.x], 1);
            atomicAdd(&g_deg[d.y], 1);
            atomicAdd(&g_deg[d.z], 1);
            atomicAdd(&g_deg[d.w], 1);
        }
    } else if (b < NB_EDGE + NB_XCONV) {
        size_t i = (size_t)(b - NB_EDGE) * 256 + threadIdx.x;   // float4 index
        float4 v = ((const float4*)x)[i];
        __half2 a = __floats2half2_rn(v.x, v.y);
        __half2 c = __floats2half2_rn(v.z, v.w);
        uint2 p; p.x = *(unsigned*)&a; p.y = *(unsigned*)&c;
        *(uint2*)(g_ah + i * 4) = p;
    } else {
        size_t wi = (size_t)(b - NB_EDGE - NB_XCONV) * 256 + threadIdx.x;
        if (wi < 16384) {
            float4 v = (wi < 4096) ? ((const float4*)W_in)[wi]
                                   : ((const float4*)W_hid)[wi - 4096];
            __half2 a = __floats2half2_rn(v.x, v.y);
            __half2 c = __floats2half2_rn(v.z, v.w);
            uint2 p; p.x = *(unsigned*)&a; p.y = *(unsigned*)&c;
            *(uint2*)(g_wh + wi * 4) = p;
        }
    }
}

// ---------------- fused scan (warp-parallel decoupled lookback) --------------
__global__ void k_scan_fused() {
    __shared__ int sm[1024];
    __shared__ int s_prefix;
    const int b = blockIdx.x;
    const int i = b * 1024 + threadIdx.x;
    const int v = (i < NN) ? g_deg[i] : 0;
    sm[threadIdx.x] = v;
    __syncthreads();
    for (int d = 1; d < 1024; d <<= 1) {
        int t = (threadIdx.x >= d) ? sm[threadIdx.x - d] : 0;
        __syncthreads();
        sm[threadIdx.x] += t;
        __syncthreads();
    }
    if (threadIdx.x < 32) {
        const unsigned total = (unsigned)sm[1023];
        const int lane = threadIdx.x;
        if (b == 0) {
            if (lane == 0) {
                atomicExch(&g_scanstate[0], (2ULL << 32) | total);   // inclusive
                s_prefix = 0;
            }
        } else {
            if (lane == 0)
                atomicExch(&g_scanstate[b], (1ULL << 32) | total);   // aggregate
            // warp-parallel lookback: 32 predecessor states per round
            int excl = 0;
            int pb = b - 1;
            while (true) {
                int idx = pb - lane;                                  // lane0 nearest
                unsigned long long st = (idx >= 0)
                    ? atomicAdd(&g_scanstate[idx], 0ULL) : (2ULL << 32);
                unsigned flag = (unsigned)(st >> 32);
                unsigned ball2 = __ballot_sync(0xffffffffu, flag == 2u);
                unsigned ball0 = __ballot_sync(0xffffffffu, flag == 0u);
                if (ball2) {
                    int first2 = __ffs(ball2) - 1;
                    if (ball0 & ((1u << first2) - 1)) continue;       // gap pending
                    int val = (lane <= first2) ? (int)(st & 0xffffffffu) : 0;
#pragma unroll
                    for (int o = 16; o; o >>= 1)
                        val += __shfl_down_sync(0xffffffffu, val, o);
                    excl += __shfl_sync(0xffffffffu, val, 0);
                    break;
                }
                if (ball0) continue;                                  // wait
                int val = (int)(st & 0xffffffffu);                    // all flag1
#pragma unroll
                for (int o = 16; o; o >>= 1)
                    val += __shfl_down_sync(0xffffffffu, val, o);
                excl += __shfl_sync(0xffffffffu, val, 0);
                pb -= 32;
            }
            if (lane == 0) {
                atomicExch(&g_scanstate[b], (2ULL << 32) | (unsigned)(total + excl));
                s_prefix = excl;
            }
        }
    }
    __syncthreads();
    const int incl = sm[threadIdx.x] + s_prefix;
    if (i < NN) {
        int excl_i = incl - v;
        g_off[i]  = excl_i;
        g_fill[i] = excl_i;
        if (i == NN - 1) g_off[NN] = incl;
    }
}

// ---------------- CSR fill: 8 independent edge chains per thread -------------
__global__ void k_fill(const int* __restrict__ ei) {
    int t = blockIdx.x * blockDim.x + threadIdx.x;
    if (t < NE / 8) {
        int4 s0 = ((const int4*)ei)[2 * t];
        int4 s1 = ((const int4*)ei)[2 * t + 1];
        int4 d0 = ((const int4*)(ei + NE))[2 * t];
        int4 d1 = ((const int4*)(ei + NE))[2 * t + 1];
        int p;
        p = atomicAdd(&g_fill[d0.x], 1); g_csr[p] = s0.x;
        p = atomicAdd(&g_fill[d0.y], 1); g_csr[p] = s0.y;
        p = atomicAdd(&g_fill[d0.z], 1); g_csr[p] = s0.z;
        p = atomicAdd(&g_fill[d0.w], 1); g_csr[p] = s0.w;
        p = atomicAdd(&g_fill[d1.x], 1); g_csr[p] = s1.x;
        p = atomicAdd(&g_fill[d1.y], 1); g_csr[p] = s1.y;
        p = atomicAdd(&g_fill[d1.z], 1); g_csr[p] = s1.z;
        p = atomicAdd(&g_fill[d1.w], 1); g_csr[p] = s1.w;
    }
}

// ---------------- tensor-core GEMM: g = fp16( dinv * (A @ W) ) ---------------
// Whole-K resident; A fp16; W fp16. CTA = 128x64. 4 CTAs/SM (32 warps).
__global__ void __launch_bounds__(256, 4) k_gemm_tc(int layer) {
    extern __shared__ __half smh[];
    __half* As = smh;                        // [128][SA_A]
    __half* Wh = smh + A_HALVES;             // [128][SA_W]
    const int col0 = (blockIdx.x & 1) * 64;
    const int row0 = (blockIdx.x >> 1) * 128;
    const __half* Wbh = g_wh + (size_t)layer * 16384 + col0;
    const int tid = threadIdx.x;

    // single burst: whole A tile (128x128) + whole W (128x64)
#pragma unroll
    for (int o = tid; o < 2048; o += 256) {           // A: 128 rows x 16 segs
        int r = o >> 4, seg = (o & 15) * 8;
        int grow = row0 + r;
        if (grow < NN)
            cpa16(As + r * SA_A + seg, g_ah + (size_t)grow * 128 + seg);
    }
#pragma unroll
    for (int o = tid; o < 1024; o += 256) {           // W: 128 rows x 8 segs
        int kr = o >> 3, seg = (o & 7) * 8;
        cpa16(Wh + kr * SA_W + seg, Wbh + (size_t)kr * 128 + seg);
    }
    asm volatile("cp.async.commit_group;");

    const int lane = tid & 31, wid = tid >> 5;
    const int wm = wid >> 1, wn = wid & 1;               // 4x2 warp grid
    const int g = lane >> 2, t2 = (lane & 3) << 1;
    const int lr = lane & 7, sel = lane >> 3;
    const int a_row_off = (sel & 1) * 8;
    const int a_col_off = (sel & 2) * 4;
    const int w_krow = lane & 15;
    const int w_noff = (lane >> 4) * 8;

    float acc[2][4][4];
#pragma unroll
    for (int mt = 0; mt < 2; mt++)
#pragma unroll
        for (int nt = 0; nt < 4; nt++)
#pragma unroll
            for (int q = 0; q < 4; q++) acc[mt][nt][q] = 0.f;

    asm volatile("cp.async.wait_group 0;");
    __syncthreads();

#pragma unroll
    for (int ks = 0; ks < 8; ks++) {
        const int kc = ks * 16;
        unsigned bh2[2][4];
#pragma unroll
        for (int nh = 0; nh < 2; nh++) {
            const __half* pw = Wh + (kc + w_krow) * SA_W + wn * 32 + nh * 16 + w_noff;
            ldsm_x4t(bh2[nh], pw);
        }
#pragma unroll
        for (int mt = 0; mt < 2; mt++) {
            const int m0 = wm * 32 + mt * 16;
            unsigned a_[4];
            ldsm_x4(a_, As + (m0 + lr + a_row_off) * SA_A + kc + a_col_off);
#pragma unroll
            for (int nt = 0; nt < 4; nt++) {
                unsigned bhf[2] = {bh2[nt >> 1][(nt & 1) * 2],
                                   bh2[nt >> 1][(nt & 1) * 2 + 1]};
                mma16816(acc[mt][nt], a_, bhf);   // A @ W
            }
        }
    }

    // epilogue: scale by dinv (from deg), pack fp16, store
#pragma unroll
    for (int mt = 0; mt < 2; mt++) {
        int r0 = row0 + wm * 32 + mt * 16 + g;
        int r1 = r0 + 8;
        float d0 = (r0 < NN) ? rsqrtf((float)(g_deg[r0] + 1)) : 0.f;
        float d1 = (r1 < NN) ? rsqrtf((float)(g_deg[r1] + 1)) : 0.f;
#pragma unroll
        for (int nt = 0; nt < 4; nt++) {
            int n = col0 + wn * 32 + nt * 8 + t2;
            if (r0 < NN) {
                __half2 p = __floats2half2_rn(acc[mt][nt][0] * d0, acc[mt][nt][1] * d0);
                *(__half2*)(g_gh + (size_t)r0 * 128 + n) = p;
            }
            if (r1 < NN) {
                __half2 p = __floats2half2_rn(acc[mt][nt][2] * d1, acc[mt][nt][3] * d1);
                *(__half2*)(g_gh + (size_t)r1 * 128 + n) = p;
            }
        }
    }
}

// ---------------- aggregation (gather CSR; 4 edges in flight) ---------------
__global__ void __launch_bounds__(256) k_agg(const float* __restrict__ bias) {
    int n = (blockIdx.x * blockDim.x + threadIdx.x) >> 5;
    int lane = threadIdx.x & 31;
    if (n >= NN) return;
    const uint2* gb = (const uint2*)g_gh;       // 8B units; row stride = 32
    uint2 sv = gb[(size_t)n * 32 + lane];       // self-loop term
    __half2 h0 = *(__half2*)&sv.x, h1 = *(__half2*)&sv.y;
    float2 f0 = __half22float2(h0), f1 = __half22float2(h1);
    float4 acc = make_float4(f0.x, f0.y, f1.x, f1.y);

    int s = g_off[n], e = g_off[n + 1];
    for (int base = s; base < e; base += 32) {
        int cnt = e - base; if (cnt > 32) cnt = 32;
        int id = (lane < cnt) ? g_csr[base + lane] : 0;
        int j = 0;
        for (; j + 4 <= cnt; j += 4) {          // two independent HADD2 pairs
            int s0 = __shfl_sync(0xffffffffu, id, j);
            int s1 = __shfl_sync(0xffffffffu, id, j + 1);
            int s2 = __shfl_sync(0xffffffffu, id, j + 2);
            int s3 = __shfl_sync(0xffffffffu, id, j + 3);
            uint2 va = gb[(size_t)s0 * 32 + lane];
            uint2 vb = gb[(size_t)s1 * 32 + lane];
            uint2 vc = gb[(size_t)s2 * 32 + lane];
            uint2 vd = gb[(size_t)s3 * 32 + lane];
            __half2 p0 = __hadd2(*(__half2*)&va.x, *(__half2*)&vb.x);
            __half2 p1 = __hadd2(*(__half2*)&va.y, *(__half2*)&vb.y);
            __half2 q0 = __hadd2(*(__half2*)&vc.x, *(__half2*)&vd.x);
            __half2 q1 = __hadd2(*(__half2*)&vc.y, *(__half2*)&vd.y);
            float2 a0 = __half22float2(p0), a1 = __half22float2(p1);
            float2 b0 = __half22float2(q0), b1 = __half22float2(q1);
            acc.x += a0.x + b0.x; acc.y += a0.y + b0.y;
            acc.z += a1.x + b1.x; acc.w += a1.y + b1.y;
        }
        if (j + 2 <= cnt) {
            int s0 = __shfl_sync(0xffffffffu, id, j);
            int s1 = __shfl_sync(0xffffffffu, id, j + 1);
            uint2 va = gb[(size_t)s0 * 32 + lane];
            uint2 vb = gb[(size_t)s1 * 32 + lane];
            __half2 p0 = __hadd2(*(__half2*)&va.x, *(__half2*)&vb.x);
            __half2 p1 = __hadd2(*(__half2*)&va.y, *(__half2*)&vb.y);
            float2 a0 = __half22float2(p0), a1 = __half22float2(p1);
            acc.x += a0.x; acc.y += a0.y; acc.z += a1.x; acc.w += a1.y;
            j += 2;
        }
        if (j < cnt) {
            int s0 = __shfl_sync(0xffffffffu, id, j);
            uint2 va = gb[(size_t)s0 * 32 + lane];
            float2 a0 = __half22float2(*(__half2*)&va.x);
            float2 a1 = __half22float2(*(__half2*)&va.y);
            acc.x += a0.x; acc.y += a0.y; acc.z += a1.x; acc.w += a1.y;
        }
    }
    float dn = rsqrtf((float)(g_deg[n] + 1));
    float4 bb = *(const float4*)(bias + lane * 4);
    __half2 o0 = __floats2half2_rn(acc.x * dn + bb.x, acc.y * dn + bb.y);
    __half2 o1 = __floats2half2_rn(acc.z * dn + bb.z, acc.w * dn + bb.w);
    uint2 p; p.x = *(unsigned*)&o0; p.y = *(unsigned*)&o1;
    *(uint2*)(g_ah + (size_t)n * 128 + lane * 4) = p;
}

// ---------------- mean pool per graph + output head -------------------------
__global__ void __launch_bounds__(128) k_pool(const int* __restrict__ batch,
                                              const float* __restrict__ Wout,
                                              const float* __restrict__ bout,
                                              float* __restrict__ out) {
    int gid = blockIdx.x;
    int c = threadIdx.x;
    int lo = 0, hi = NN;
    while (lo < hi) { int m = (lo + hi) >> 1; if (batch[m] < gid) lo = m + 1; else hi = m; }
    int start = lo;
    hi = NN;
    while (lo < hi) { int m = (lo + hi) >> 1; if (batch[m] < gid + 1) lo = m + 1; else hi = m; }
    int end = lo;

    float s = 0.f;
    for (int r = start; r < end; r++)
        s += __half2float(g_ah[(size_t)r * 128 + c]);
    __shared__ float pooled[128];
    int cnt = end - start;
    pooled[c] = (cnt > 0) ? s / (float)cnt : 0.f;
    __syncthreads();
    if (c < NOUT) {
        float a = bout[c];
#pragma unroll 8
        for (int k = 0; k < 128; k++) a += pooled[k] * Wout[k * NOUT + c];
        out[gid * NOUT + c] = a;
    }
}

// ---------------- launch ------------------------------------------------------
extern "C" void kernel_launch(void* const* d_in, const int* in_sizes, int n_in,
                              void* d_out, int out_size) {
    const float* x      = (const float*)d_in[0];
    const int*   ei     = (const int*)d_in[1];     // int32 (JAX x64 disabled)
    const int*   batch  = (const int*)d_in[2];     // int32
    const float* W_in   = (const float*)d_in[3];
    const float* b_in   = (const float*)d_in[4];
    const float* W_hid  = (const float*)d_in[5];
    const float* b_hid  = (const float*)d_in[6];
    const float* W_out  = (const float*)d_in[7];
    const float* b_out  = (const float*)d_in[8];
    float* out = (float*)d_out;

    cudaFuncSetAttribute(k_gemm_tc, cudaFuncAttributeMaxDynamicSharedMemorySize,
                         SMEM_BYTES);

    const int agg_blocks = (NN * 32 + 255) / 256;

    // gemm0 kept as 4th launch (ncu capture slot)
    k_zero<<<NB_ZERO, 256>>>();
    k_prep<<<NB_EDGE + NB_XCONV + 64, 256>>>(ei, x, W_in, W_hid);
    k_scan_fused<<<NB_SCAN, 1024>>>();
    k_gemm_tc<<<GEMM_BLOCKS, 256, SMEM_BYTES>>>(0);          // <- profiled
    k_fill<<<NB_FILL, 256>>>(ei);

    k_agg<<<agg_blocks, 256>>>(b_in);
    for (int i = 0; i < 3; i++) {
        k_gemm_tc<<<GEMM_BLOCKS, 256, SMEM_BYTES>>>(i + 1);
        k_agg<<<agg_blocks, 256>>>(b_hid + (size_t)i * 128);
    }

    k_pool<<<NG, 128>>>(batch, W_out, b_out, out);
}